// round 1
// baseline (speedup 1.0000x reference)
#include <cuda_runtime.h>
#include <cub/cub.cuh>
#include <cstdint>

// Problem constants: logits [8,19,384,384] f32 NCHW, labels [8,384,384] int (64 or 32)
#define NUM_C     19
#define HW        147456            // 384*384
#define NPIX      1179648           // 8*384*384
#define TOTAL_K   (NUM_C * NPIX)    // 22413312
#define CHUNK     4096
#define NCHUNK    (TOTAL_K / CHUNK) // 5472
#define CPC       (NPIX / CHUNK)    // 288 chunks per class
#define TEMP_CAP  (size_t)(128u * 1024u * 1024u)

// Static device scratch (allocation-free rule: __device__ globals)
__device__ __align__(256) unsigned long long g_keys_a[TOTAL_K];
__device__ __align__(256) unsigned long long g_keys_b[TOTAL_K];
__device__ __align__(256) unsigned char      g_temp[TEMP_CAP];
__device__ int    g_chunk_sum[NCHUNK];
__device__ int    g_chunk_off[NCHUNK];
__device__ int    g_seg_total[NUM_C];
__device__ double g_loss_total;
__device__ int    g_lab32;   // 1 if labels are int32, 0 if int64

// ---------------------------------------------------------------------------
// Detect label element width. int64 labels in [0,19) have zero high words;
// int32 data reinterpreted as int64 packs two labels -> huge values.
// Only scan NPIX/2 int64 slots so we never read past an int32-sized buffer.
__global__ void detect_kernel(const long long* __restrict__ L) {
    int bad = 0;
    for (int i = blockIdx.x * blockDim.x + threadIdx.x; i < NPIX / 2;
         i += gridDim.x * blockDim.x) {
        long long v = L[i];
        if (v < -1000000LL || v > 1000000LL) bad = 1;
    }
    if (__syncthreads_or(bad)) {
        if (threadIdx.x == 0) atomicOr(&g_lab32, 1);
    }
}

// ---------------------------------------------------------------------------
// Softmax over C per pixel; emit per-(class,pixel) sort key:
//   key = (class << 31) | (float_bits(err) << 1) | fg
// err in [0,1] -> float bits fit in 30 bits; err recovered EXACTLY by >>1.
__global__ void __launch_bounds__(256) make_keys_kernel(
    const float* __restrict__ logits, const void* __restrict__ labels,
    unsigned long long* __restrict__ keys) {
    int p = blockIdx.x * blockDim.x + threadIdx.x;
    if (p >= NPIX) return;
    int n = p / HW;
    int hw = p - n * HW;
    const float* base = logits + (size_t)n * NUM_C * HW + hw;

    float v[NUM_C];
    float m = -1e30f;
#pragma unroll
    for (int c = 0; c < NUM_C; c++) {
        v[c] = base[(size_t)c * HW];
        m = fmaxf(m, v[c]);
    }
    float s = 0.f;
#pragma unroll
    for (int c = 0; c < NUM_C; c++) {
        v[c] = expf(v[c] - m);
        s += v[c];
    }
    float inv = 1.0f / s;

    long long lab;
    if (g_lab32) lab = (long long)((const int*)labels)[p];
    else         lab = ((const long long*)labels)[p];
    bool valid = (lab >= 0 && lab < NUM_C);

#pragma unroll
    for (int c = 0; c < NUM_C; c++) {
        float prob = v[c] * inv;
        unsigned int fg;
        float e;
        if (!valid) { fg = 0u; e = 0.f; }
        else {
            fg = (lab == (long long)c) ? 1u : 0u;
            e = fg ? (1.0f - prob) : prob;
        }
        unsigned int eb = __float_as_uint(e);   // <= 0x3F800000 (30 bits)
        unsigned long long key =
            ((unsigned long long)c << 31) |
            ((unsigned long long)eb << 1) | (unsigned long long)fg;
        keys[(size_t)c * NPIX + p] = key;
    }
}

// ---------------------------------------------------------------------------
// Per-chunk fg counts over the sorted keys.
__global__ void __launch_bounds__(256) chunk_sums_kernel(
    const unsigned long long* __restrict__ keys) {
    int b = blockIdx.x, t = threadIdx.x;
    const unsigned long long* base = keys + (size_t)b * CHUNK;
    int s = 0;
#pragma unroll
    for (int i = 0; i < CHUNK / 256; i++) s += (int)(base[t + i * 256] & 1ull);
#pragma unroll
    for (int d = 16; d; d >>= 1) s += __shfl_down_sync(~0u, s, d);
    __shared__ int ws[8];
    if ((t & 31) == 0) ws[t >> 5] = s;
    __syncthreads();
    if (t == 0) {
        int tot = 0;
#pragma unroll
        for (int w = 0; w < 8; w++) tot += ws[w];
        g_chunk_sum[b] = tot;
    }
}

// Per-class exclusive scan of 288 chunk sums (one warp per class segment).
__global__ void scan_chunks_kernel() {
    int k = blockIdx.x;          // segment index (class order irrelevant: mean)
    int lane = threadIdx.x;      // 32 threads, 9 items each
    int base = k * CPC;
    int v[9];
#pragma unroll
    for (int i = 0; i < 9; i++) v[i] = g_chunk_sum[base + lane * 9 + i];
    int lsum = 0;
#pragma unroll
    for (int i = 0; i < 9; i++) { int t = v[i]; v[i] = lsum; lsum += t; }
    int x = lsum;
#pragma unroll
    for (int d = 1; d < 32; d <<= 1) {
        int y = __shfl_up_sync(~0u, x, d);
        if (lane >= d) x += y;
    }
    int excl = x - lsum;
#pragma unroll
    for (int i = 0; i < 9; i++) g_chunk_off[base + lane * 9 + i] = excl + v[i];
    if (lane == 31) g_seg_total[k] = x;   // total fg for this class
}

// ---------------------------------------------------------------------------
// Fused Lovasz gradient + weighted sum:
//   J(i,s) = 1 - (g-s)/(g + (i+1) - s);  grad_i = J(i,s_i) - J(i-1, s_i-fg_i)
//   loss_seg += e_i * grad_i   (double accumulation)
__global__ void __launch_bounds__(256) loss_kernel(
    const unsigned long long* __restrict__ keys) {
    int b = blockIdx.x, t = threadIdx.x;
    int k = b / CPC;
    int cic = b - k * CPC;
    float gf = (float)g_seg_total[k];
    int off = g_chunk_off[b];
    const unsigned long long* base = keys + (size_t)b * CHUNK;

    unsigned long long kv[16];
#pragma unroll
    for (int i = 0; i < 16; i += 2) {
        ulonglong2 u = *reinterpret_cast<const ulonglong2*>(base + t * 16 + i);
        kv[i] = u.x; kv[i + 1] = u.y;
    }
    int tsum = 0;
#pragma unroll
    for (int i = 0; i < 16; i++) tsum += (int)(kv[i] & 1ull);

    // block exclusive scan of per-thread fg sums
    int lane = t & 31, wid = t >> 5;
    int x = tsum;
#pragma unroll
    for (int d = 1; d < 32; d <<= 1) {
        int y = __shfl_up_sync(~0u, x, d);
        if (lane >= d) x += y;
    }
    __shared__ int wsum[8];
    if (lane == 31) wsum[wid] = x;
    __syncthreads();
    int wbase = 0;
#pragma unroll
    for (int w = 0; w < 8; w++) if (w < wid) wbase += wsum[w];
    int excl = off + wbase + (x - tsum);   // fg before this thread's first item
    int i0 = cic * CHUNK + t * 16;         // global-in-class index of first item

    double acc = 0.0;
    int run = 0;
#pragma unroll
    for (int i = 0; i < 16; i++) {
        int fg = (int)(kv[i] & 1ull);
        run += fg;
        int s = excl + run;                              // inclusive cumsum
        int gi = i0 + i;                                 // 0-based rank
        unsigned int eb = (unsigned int)((kv[i] >> 1) & 0x3FFFFFFFull);
        float e = __uint_as_float(eb);                   // exact error value
        float sf = (float)s;
        float Jc = 1.0f - (gf - sf) / (gf + (float)(gi + 1) - sf);
        float Jp = 0.0f;
        if (gi != 0) {
            float sp = (float)(s - fg);
            Jp = 1.0f - (gf - sp) / (gf + (float)gi - sp);
        }
        acc += (double)(e * (Jc - Jp));
    }

    __shared__ double dsh[256];
    dsh[t] = acc;
    __syncthreads();
    for (int d = 128; d; d >>= 1) {
        if (t < d) dsh[t] += dsh[t + d];
        __syncthreads();
    }
    if (t == 0) atomicAdd(&g_loss_total, dsh[0]);
}

__global__ void finalize_kernel(float* __restrict__ out) {
    out[0] = (float)(g_loss_total / (double)NUM_C);
}

// ---------------------------------------------------------------------------
extern "C" void kernel_launch(void* const* d_in, const int* in_sizes, int n_in,
                              void* d_out, int out_size) {
    // logits is the larger input (22.4M elems) regardless of metadata order
    int li = (in_sizes[0] > in_sizes[1]) ? 0 : 1;
    const float* logits = (const float*)d_in[li];
    const void* labels = d_in[1 - li];
    float* out = (float*)d_out;

    void *pa, *pb, *pt, *pl, *pf;
    cudaGetSymbolAddress(&pa, g_keys_a);
    cudaGetSymbolAddress(&pb, g_keys_b);
    cudaGetSymbolAddress(&pt, g_temp);
    cudaGetSymbolAddress(&pl, g_loss_total);
    cudaGetSymbolAddress(&pf, g_lab32);

    cudaMemsetAsync(pf, 0, sizeof(int));
    cudaMemsetAsync(pl, 0, sizeof(double));

    detect_kernel<<<64, 256>>>((const long long*)labels);

    make_keys_kernel<<<NPIX / 256, 256>>>(logits, labels,
                                          (unsigned long long*)pa);

    cub::DoubleBuffer<unsigned long long> db((unsigned long long*)pa,
                                             (unsigned long long*)pb);
    size_t tb = TEMP_CAP;
    cub::DeviceRadixSort::SortKeysDescending(pt, tb, db, (int)TOTAL_K, 0, 36);

    const unsigned long long* sorted = db.Current();
    chunk_sums_kernel<<<NCHUNK, 256>>>(sorted);
    scan_chunks_kernel<<<NUM_C, 32>>>();
    loss_kernel<<<NCHUNK, 256>>>(sorted);
    finalize_kernel<<<1, 1>>>(out);
}

// round 2
// speedup vs baseline: 4.9584x; 4.9584x over previous
#include <cuda_runtime.h>
#include <cstdint>

// Lovasz-Softmax: histogram (counting-sort) formulation — no radix sort.
// logits [8,19,384,384] f32 NCHW, labels [8,384,384] int64 (or int32)
#define NUM_C   19
#define HW      147456              // 384*384
#define NPIX    1179648             // 8*384*384
#define QSHIFT  10                  // drop 10 of 30 float-pattern bits
#define NBINS   (1u << 20)          // covers q <= 0x3F800000>>10 = 0xFE000
#define CHB     4096                // bins per chunk
#define NCH     256                 // chunks per class (2^20 / 4096)

// Static device scratch (allocation-free rule)
__device__ __align__(256) unsigned g_cnt[(size_t)NUM_C * NBINS * 2]; // [c][q][fg]
__device__ uint2    g_chs[NUM_C * NCH];    // per-chunk (fg_sum, tot_sum)
__device__ uint2    g_choff[NUM_C * NCH];  // exclusive (fg_off, tot_off)
__device__ unsigned g_gtot[NUM_C];         // total fg per class
__device__ double   g_loss_total;
__device__ int      g_lab32;               // labels are int32?

// ---------------------------------------------------------------------------
// Detect label width: int64 labels in [0,19) never look like packed int32s.
__global__ void detect_kernel(const long long* __restrict__ L) {
    int bad = 0;
    for (int i = blockIdx.x * blockDim.x + threadIdx.x; i < NPIX / 2;
         i += gridDim.x * blockDim.x) {
        long long v = L[i];
        if (v < -1000000LL || v > 1000000LL) bad = 1;
    }
    if (__syncthreads_or(bad)) {
        if (threadIdx.x == 0) atomicOr(&g_lab32, 1);
    }
}

// ---------------------------------------------------------------------------
// Softmax per pixel; bump histogram counter for (class, q(err), fg).
__global__ void __launch_bounds__(256) hist_kernel(
    const float* __restrict__ logits, const void* __restrict__ labels,
    unsigned* __restrict__ cnt) {
    int p = blockIdx.x * blockDim.x + threadIdx.x;
    if (p >= NPIX) return;
    int n = p / HW;
    int hw = p - n * HW;
    const float* base = logits + (size_t)n * NUM_C * HW + hw;

    float v[NUM_C];
    float m = -1e30f;
#pragma unroll
    for (int c = 0; c < NUM_C; c++) {
        v[c] = base[(size_t)c * HW];
        m = fmaxf(m, v[c]);
    }
    float s = 0.f;
#pragma unroll
    for (int c = 0; c < NUM_C; c++) {
        v[c] = __expf(v[c] - m);
        s += v[c];
    }
    float inv = 1.0f / s;

    long long lab;
    if (g_lab32) lab = (long long)((const int*)labels)[p];
    else         lab = ((const long long*)labels)[p];
    bool valid = (lab >= 0 && lab < NUM_C);

#pragma unroll
    for (int c = 0; c < NUM_C; c++) {
        float prob = v[c] * inv;
        unsigned fg;
        float e;
        if (!valid) { fg = 0u; e = 0.f; }
        else {
            fg = (lab == (long long)c) ? 1u : 0u;
            e = fg ? (1.0f - prob) : prob;
        }
        unsigned q = __float_as_uint(e) >> QSHIFT;
        unsigned idx = (((unsigned)c << 20) | q) * 2u + fg;
        atomicAdd(&cnt[idx], 1u);   // result unused -> RED (no return)
    }
}

// ---------------------------------------------------------------------------
// Pass A: per-(class,chunk) sums of fg and total counts.
__global__ void __launch_bounds__(256) chunk_sums_kernel(
    const unsigned* __restrict__ cnt) {
    int b = blockIdx.x, t = threadIdx.x;
    int c = b / NCH, cc = b - c * NCH;
    unsigned qlo = NBINS - (unsigned)(cc + 1) * CHB;   // order irrelevant here
    const uint4* p4 = (const uint4*)(cnt +
        (((size_t)c << 20) + qlo + (unsigned)t * 16u) * 2u);
    unsigned nf = 0, tot = 0;
#pragma unroll
    for (int i = 0; i < 8; i++) {
        uint4 u = p4[i];            // (bg,fg,bg,fg)
        nf  += u.y + u.w;
        tot += u.x + u.y + u.z + u.w;
    }
    unsigned long long x = ((unsigned long long)tot << 32) | nf;
#pragma unroll
    for (int d = 16; d; d >>= 1) x += __shfl_down_sync(~0u, x, d);
    __shared__ unsigned long long ws[8];
    if ((t & 31) == 0) ws[t >> 5] = x;
    __syncthreads();
    if (t == 0) {
        unsigned long long tt = 0;
#pragma unroll
        for (int w = 0; w < 8; w++) tt += ws[w];
        g_chs[b] = make_uint2((unsigned)(tt & 0xffffffffu), (unsigned)(tt >> 32));
    }
}

// Pass B: per-class exclusive scan of 256 chunk sums (descending-e chunk order
// == ascending cc, since cc=0 holds the highest q range).
__global__ void scan_kernel() {
    int c = blockIdx.x, t = threadIdx.x;   // 256 threads
    uint2 v = g_chs[c * NCH + t];
    unsigned long long x = ((unsigned long long)v.y << 32) | v.x;
    __shared__ unsigned long long sh[256];
    sh[t] = x;
    __syncthreads();
    for (int d = 1; d < 256; d <<= 1) {
        unsigned long long y = (t >= d) ? sh[t - d] : 0ull;
        __syncthreads();
        sh[t] += y;
        __syncthreads();
    }
    unsigned long long incl = sh[t];
    unsigned long long excl = incl - x;
    g_choff[c * NCH + t] =
        make_uint2((unsigned)(excl & 0xffffffffu), (unsigned)(excl >> 32));
    if (t == 255) g_gtot[c] = (unsigned)(incl & 0xffffffffu);
}

// ---------------------------------------------------------------------------
// Pass C: walk buckets in descending q; per nonempty bucket the tied block's
// contribution telescopes:  e_hat * (J(end) - J(start-1)),
// J(i,s) = 1 - (g-s)/(g + (i+1) - s), monotone in rank.
__global__ void __launch_bounds__(256) loss_kernel(
    const unsigned* __restrict__ cnt) {
    int b = blockIdx.x, t = threadIdx.x;
    int c = b / NCH, cc = b - c * NCH;
    float gf = (float)g_gtot[c];
    uint2 off = g_choff[b];

    // thread t owns descending positions j = cc*CHB + t*16 + [0..15]
    // -> q in [qlo, qlo+15] consumed from high q to low q
    int qlo = (int)NBINS - (cc * CHB + t * 16) - 16;
    const uint4* p4 = (const uint4*)(cnt + (((size_t)c << 20) + qlo) * 2u);
    unsigned nf[16], nb[16];
#pragma unroll
    for (int i = 0; i < 8; i++) {
        uint4 u = p4[i];
        nb[2 * i] = u.x; nf[2 * i] = u.y;
        nb[2 * i + 1] = u.z; nf[2 * i + 1] = u.w;
    }
    unsigned tf = 0, tt = 0;
#pragma unroll
    for (int i = 0; i < 16; i++) { tf += nf[i]; tt += nf[i] + nb[i]; }

    // block exclusive scan of packed (tot<<32 | fg)
    int lane = t & 31, wid = t >> 5;
    unsigned long long x = ((unsigned long long)tt << 32) | tf;
    unsigned long long self = x;
#pragma unroll
    for (int d = 1; d < 32; d <<= 1) {
        unsigned long long y = __shfl_up_sync(~0u, x, d);
        if (lane >= d) x += y;
    }
    __shared__ unsigned long long wsum[8];
    if (lane == 31) wsum[wid] = x;
    __syncthreads();
    unsigned long long wbase = 0;
#pragma unroll
    for (int w = 0; w < 8; w++) if (w < wid) wbase += wsum[w];
    unsigned long long excl = wbase + (x - self);

    int a  = (int)off.y + (int)(excl >> 32);          // rank offset (0-based)
    int S0 = (int)off.x + (int)(excl & 0xffffffffu);  // fg cumsum before

    double acc = 0.0;
#pragma unroll
    for (int k = 15; k >= 0; k--) {        // descending q
        unsigned f = nf[k], bgc = nb[k];
        unsigned nn = f + bgc;
        if (nn) {
            int q = qlo + k;
            float eh = __uint_as_float(((unsigned)q << QSHIFT) +
                                       (1u << (QSHIFT - 1)));  // bucket midpoint
            float Jp = 0.f;
            if (a > 0) {
                float sp = (float)S0;
                Jp = 1.f - __fdividef(gf - sp, gf + (float)a - sp);
            }
            int ae = a + (int)nn;
            int se = S0 + (int)f;
            float sf = (float)se;
            float Je = 1.f - __fdividef(gf - sf, gf + (float)ae - sf);
            acc += (double)(eh * (Je - Jp));
            a = ae; S0 = se;
        } else {
            // empty bucket: rank/fg unchanged
        }
    }

    __shared__ double dsh[256];
    dsh[t] = acc;
    __syncthreads();
    for (int d = 128; d; d >>= 1) {
        if (t < d) dsh[t] += dsh[t + d];
        __syncthreads();
    }
    if (t == 0) atomicAdd(&g_loss_total, dsh[0]);
}

__global__ void finalize_kernel(float* __restrict__ out) {
    out[0] = (float)(g_loss_total / (double)NUM_C);
}

// ---------------------------------------------------------------------------
extern "C" void kernel_launch(void* const* d_in, const int* in_sizes, int n_in,
                              void* d_out, int out_size) {
    int li = (in_sizes[0] > in_sizes[1]) ? 0 : 1;
    const float* logits = (const float*)d_in[li];
    const void* labels = d_in[1 - li];
    float* out = (float*)d_out;

    void *pc, *pl, *pf;
    cudaGetSymbolAddress(&pc, g_cnt);
    cudaGetSymbolAddress(&pl, g_loss_total);
    cudaGetSymbolAddress(&pf, g_lab32);

    cudaMemsetAsync(pc, 0, (size_t)NUM_C * NBINS * 2 * sizeof(unsigned));
    cudaMemsetAsync(pf, 0, sizeof(int));
    cudaMemsetAsync(pl, 0, sizeof(double));

    detect_kernel<<<64, 256>>>((const long long*)labels);
    hist_kernel<<<NPIX / 256, 256>>>(logits, labels, (unsigned*)pc);
    chunk_sums_kernel<<<NUM_C * NCH, 256>>>((const unsigned*)pc);
    scan_kernel<<<NUM_C, 256>>>();
    loss_kernel<<<NUM_C * NCH, 256>>>((const unsigned*)pc);
    finalize_kernel<<<1, 1>>>(out);
}

// round 3
// speedup vs baseline: 8.0271x; 1.6189x over previous
#include <cuda_runtime.h>
#include <cstdint>

// Lovasz-Softmax via L2-resident counting histogram. No sort, no memsets.
// logits [8,19,384,384] f32 NCHW, labels [8,384,384] int64 (or int32)
#define NUM_C   19
#define HW      147456
#define NPIX    1179648
#define QLO     876544u            // ((107<<23)>>10): e = 2^-20 floor bucket
#define NBINS   163840             // q in [0, NBINS); 80 * 2048; top = e<1.0
#define CHB     2048
#define NCH     80                 // chunks per class
#define STRIDE  (NBINS * 2)        // u32 per class (fg/bg interleaved)
#define EMINF   9.5367431640625e-07f   // 2^-20
#define EMAXF   0.99999994f            // largest float < 1.0
#define L2E     1.4426950408889634f

typedef unsigned long long ull;

// Static device scratch; zero on load, and every launch restores zeros.
__device__ __align__(256) unsigned g_cnt[(size_t)NUM_C * STRIDE];  // 24.9 MB
__device__ uint2    g_chs[NUM_C * NCH];
__device__ uint2    g_choff[NUM_C * NCH];
__device__ unsigned g_gtot[NUM_C];
__device__ double   g_loss_total;   // reset by finalize
__device__ int      g_lab32;        // reset by finalize

__device__ __forceinline__ float ex2f(float x) {
    float y; asm("ex2.approx.f32 %0, %1;" : "=f"(y) : "f"(x)); return y;
}
__device__ __forceinline__ float rcpf(float x) {
    float y; asm("rcp.approx.f32 %0, %1;" : "=f"(y) : "f"(x)); return y;
}
// u32 offset within a class for the bg slot of error e (fg slot = |1)
__device__ __forceinline__ unsigned eoff(float e) {
    e = fminf(fmaxf(e, EMINF), EMAXF);
    return ((__float_as_uint(e) >> 9) & ~1u) - QLO * 2u;
}

// ---------------------------------------------------------------------------
__global__ void detect_kernel(const long long* __restrict__ L) {
    int bad = 0;
    for (int i = blockIdx.x * blockDim.x + threadIdx.x; i < NPIX / 2;
         i += gridDim.x * blockDim.x) {
        long long v = L[i];
        if (v < -1000000LL || v > 1000000LL) bad = 1;
    }
    if (__syncthreads_or(bad)) {
        if (threadIdx.x == 0) atomicOr(&g_lab32, 1);
    }
}

// ---------------------------------------------------------------------------
// Softmax + histogram insert. All classes inserted as bg; fg class fixed up
// with a compensating -1 (bit-identical recompute => same bucket) and a +1
// on the fg slot. Invalid pixels are exact no-ops in the reference -> skip.
__global__ void __launch_bounds__(256) hist_kernel(
    const float* __restrict__ logits, const void* __restrict__ labels,
    unsigned* __restrict__ cnt) {
    int p = blockIdx.x * 256 + threadIdx.x;
    int n = p / HW;
    int hw = p - n * HW;
    const float* base = logits + (size_t)n * NUM_C * HW + hw;

    float v[NUM_C];
    float m = -1e30f;
#pragma unroll
    for (int c = 0; c < NUM_C; c++) {
        v[c] = base[(size_t)c * HW];
        m = fmaxf(m, v[c]);
    }
    float negam = -m * L2E;
    float s = 0.f;
#pragma unroll
    for (int c = 0; c < NUM_C; c++) {
        v[c] = ex2f(fmaf(v[c], L2E, negam));
        s += v[c];
    }
    float inv = rcpf(s);

#pragma unroll
    for (int c = 0; c < NUM_C; c++) {
        atomicAdd(cnt + (size_t)c * STRIDE + eoff(v[c] * inv), 1u);
    }

    long long lab = g_lab32 ? (long long)((const int*)labels)[p]
                            : ((const long long*)labels)[p];
    if (lab >= 0 && lab < NUM_C) {
        int lc = (int)lab;
        float x = base[(size_t)lc * HW];                 // same value reload
        float pl = ex2f(fmaf(x, L2E, negam)) * inv;      // bit-identical seq
        unsigned* cb = cnt + (size_t)lc * STRIDE;
        atomicAdd(cb + eoff(pl), 0xFFFFFFFFu);           // undo bg insert
        atomicAdd(cb + (eoff(1.0f - pl) | 1u), 1u);      // fg insert
    }
}

// ---------------------------------------------------------------------------
// Pass A: per-(class,chunk) sums of (fg, tot). Chunk cc covers descending
// positions, i.e. q in [NBINS-(cc+1)*CHB, NBINS-cc*CHB).
__global__ void __launch_bounds__(256) chunk_sums_kernel(
    const unsigned* __restrict__ cnt) {
    int b = blockIdx.x, t = threadIdx.x;
    int c = b / NCH, cc = b - c * NCH;
    unsigned qlo = NBINS - (unsigned)(cc + 1) * CHB;
    const uint4* p4 = (const uint4*)(cnt + (size_t)c * STRIDE + (size_t)qlo * 2);
    unsigned nf = 0, tot = 0;
#pragma unroll
    for (int i = 0; i < 4; i++) {
        uint4 u = p4[t + i * 256];         // (bg,fg,bg,fg)
        nf += u.y + u.w;
        tot += u.x + u.y + u.z + u.w;
    }
    ull x = ((ull)tot << 32) | nf;
#pragma unroll
    for (int d = 16; d; d >>= 1) x += __shfl_down_sync(~0u, x, d);
    __shared__ ull ws[8];
    if ((t & 31) == 0) ws[t >> 5] = x;
    __syncthreads();
    if (t == 0) {
        ull tt = 0;
#pragma unroll
        for (int w = 0; w < 8; w++) tt += ws[w];
        g_chs[b] = make_uint2((unsigned)(tt & 0xffffffffu), (unsigned)(tt >> 32));
    }
}

// Pass B: per-class exclusive scan of 80 chunk sums (ascending cc).
__global__ void scan_kernel() {
    int c = blockIdx.x, t = threadIdx.x;   // 128 threads
    ull x = 0;
    if (t < NCH) {
        uint2 v = g_chs[c * NCH + t];
        x = ((ull)v.y << 32) | v.x;
    }
    __shared__ ull sh[128];
    sh[t] = x;
    __syncthreads();
    for (int d = 1; d < 128; d <<= 1) {
        ull y = (t >= d) ? sh[t - d] : 0ull;
        __syncthreads();
        sh[t] += y;
        __syncthreads();
    }
    ull incl = sh[t];
    if (t < NCH) {
        ull excl = incl - x;
        g_choff[c * NCH + t] =
            make_uint2((unsigned)(excl & 0xffffffffu), (unsigned)(excl >> 32));
        if (t == NCH - 1) g_gtot[c] = (unsigned)(incl & 0xffffffffu);
    }
}

// ---------------------------------------------------------------------------
// Pass C: descending-q walk; nonempty bucket contributes eh*(J(end)-J(start-1))
// with J(i,s) = 1 - (g-s)/(g + (i+1) - s). Zeros counts for the next replay.
__global__ void __launch_bounds__(256) loss_kernel(unsigned* __restrict__ cnt) {
    int b = blockIdx.x, t = threadIdx.x;
    int c = b / NCH, cc = b - c * NCH;
    float gf = (float)g_gtot[c];
    uint2 off = g_choff[b];

    int j0 = cc * CHB + t * 8;             // descending position of first item
    int qbase = NBINS - j0 - 8;            // ascending q of local index 0
    uint4* p4 = (uint4*)(cnt + (size_t)c * STRIDE + (size_t)qbase * 2);
    unsigned nb[8], nf[8];
#pragma unroll
    for (int i = 0; i < 4; i++) {
        uint4 u = p4[i];
        nb[2 * i] = u.x; nf[2 * i] = u.y;
        nb[2 * i + 1] = u.z; nf[2 * i + 1] = u.w;
    }
    uint4 z = make_uint4(0u, 0u, 0u, 0u);
#pragma unroll
    for (int i = 0; i < 4; i++) p4[i] = z;  // restore zeros for next launch

    unsigned tf = 0, tt = 0;
#pragma unroll
    for (int k = 0; k < 8; k++) { tf += nf[k]; tt += nf[k] + nb[k]; }

    // block exclusive scan of packed (tot<<32 | fg)
    int lane = t & 31, wid = t >> 5;
    ull x = ((ull)tt << 32) | tf;
    ull self = x;
#pragma unroll
    for (int d = 1; d < 32; d <<= 1) {
        ull y = __shfl_up_sync(~0u, x, d);
        if (lane >= d) x += y;
    }
    __shared__ ull wsum[8];
    if (lane == 31) wsum[wid] = x;
    __syncthreads();
    ull wbase = 0;
#pragma unroll
    for (int w = 0; w < 8; w++) if (w < wid) wbase += wsum[w];
    ull excl = wbase + (x - self);

    int a  = (int)off.y + (int)(excl >> 32);          // rank before (0-based)
    int S0 = (int)off.x + (int)(excl & 0xffffffffu);  // fg cumsum before

    double acc = 0.0;
#pragma unroll
    for (int k = 7; k >= 0; k--) {          // descending q
        unsigned f = nf[k];
        unsigned nn = f + nb[k];
        if (nn) {
            unsigned mb = (((unsigned)(qbase + k) + QLO) << 10) + 512u;
            float eh = __uint_as_float(mb);             // bucket midpoint
            float Jp = 0.f;
            if (a > 0) {
                float sp = (float)S0;
                Jp = 1.f - __fdividef(gf - sp, gf + (float)a - sp);
            }
            int ae = a + (int)nn;
            int se = S0 + (int)f;
            float sf = (float)se;
            float Je = 1.f - __fdividef(gf - sf, gf + (float)ae - sf);
            acc += (double)(eh * (Je - Jp));
            a = ae; S0 = se;
        }
    }

    __shared__ double dsh[256];
    dsh[t] = acc;
    __syncthreads();
    for (int d = 128; d; d >>= 1) {
        if (t < d) dsh[t] += dsh[t + d];
        __syncthreads();
    }
    if (t == 0) atomicAdd(&g_loss_total, dsh[0]);
}

__global__ void finalize_kernel(float* __restrict__ out) {
    out[0] = (float)(g_loss_total / (double)NUM_C);
    g_loss_total = 0.0;     // restore clean state for next replay
    g_lab32 = 0;
}

// ---------------------------------------------------------------------------
extern "C" void kernel_launch(void* const* d_in, const int* in_sizes, int n_in,
                              void* d_out, int out_size) {
    int li = (in_sizes[0] > in_sizes[1]) ? 0 : 1;
    const float* logits = (const float*)d_in[li];
    const void* labels = d_in[1 - li];
    float* out = (float*)d_out;

    void* pc;
    cudaGetSymbolAddress(&pc, g_cnt);

    detect_kernel<<<64, 256>>>((const long long*)labels);
    hist_kernel<<<NPIX / 256, 256>>>(logits, labels, (unsigned*)pc);
    chunk_sums_kernel<<<NUM_C * NCH, 256>>>((const unsigned*)pc);
    scan_kernel<<<NUM_C, 128>>>();
    loss_kernel<<<NUM_C * NCH, 256>>>((unsigned*)pc);
    finalize_kernel<<<1, 1>>>(out);
}